// round 1
// baseline (speedup 1.0000x reference)
#include <cuda_runtime.h>
#include <cstdint>

#define NN 50000
#define EE 800000
#define RR 16
#define CC 128
#define K1 2048            // R*C
#define KT 2176            // K1 + C
#define EPS 1e-5f

// ---------------- scratch (module-load allocated, legal) ----------------
__device__ float g_A[(size_t)NN * K1];       // 409.6 MB aggregated features
__device__ float g_h[(size_t)NN * CC];       // hidden activations
__device__ int   g_cnt[NN * RR];
__device__ float g_winv[NN * RR];
__device__ float g_bnsum[CC];
__device__ float g_bnsq[CC];
__device__ float g_scale[CC];
__device__ float g_shift[CC];

// ---------------- init: zero counts + BN accumulators ----------------
__global__ void k_init() {
    int i = blockIdx.x * blockDim.x + threadIdx.x;
    if (i < NN * RR) g_cnt[i] = 0;
    if (i < CC) { g_bnsum[i] = 0.f; g_bnsq[i] = 0.f; }
}

// ---------------- per-(dst,rel) edge counts ----------------
__global__ void k_count(const int* __restrict__ ei, const int* __restrict__ et) {
    int e = blockIdx.x * blockDim.x + threadIdx.x;
    if (e >= EE) return;
    int dst = ei[EE + e];
    int r = et[e]; if (r > RR - 1) r = RR - 1;
    atomicAdd(&g_cnt[dst * RR + r], 1);
}

__global__ void k_winv() {
    int i = blockIdx.x * blockDim.x + threadIdx.x;
    if (i >= NN * RR) return;
    int c = g_cnt[i];
    g_winv[i] = 1.0f / (float)(c > 0 ? c : 1);
}

// ---------------- zero the aggregation buffer ----------------
__global__ void k_zeroA() {
    size_t i = (size_t)blockIdx.x * blockDim.x + threadIdx.x;   // float4 index
    size_t tot = (size_t)NN * K1 / 4;
    if (i < tot) ((float4*)g_A)[i] = make_float4(0.f, 0.f, 0.f, 0.f);
}

// ---------------- scatter: A[dst, rel*128 + c] += w * feat[src, c] ----------------
__global__ void k_scatter(const int* __restrict__ ei, const int* __restrict__ et,
                          const float* __restrict__ feat) {
    int gt = blockIdx.x * blockDim.x + threadIdx.x;
    int e = gt >> 5;
    int lane = gt & 31;
    if (e >= EE) return;
    int src = ei[e];
    int dst = ei[EE + e];
    int r = et[e]; if (r > RR - 1) r = RR - 1;
    float w = g_winv[dst * RR + r];
    const float4* xs = (const float4*)(feat + (size_t)src * CC);
    float* aout = g_A + (size_t)dst * K1 + r * CC;
    float4 v = xs[lane];
    atomicAdd(aout + lane * 4 + 0, w * v.x);
    atomicAdd(aout + lane * 4 + 1, w * v.y);
    atomicAdd(aout + lane * 4 + 2, w * v.z);
    atomicAdd(aout + lane * 4 + 3, w * v.w);
}

// ---------------- SGEMM: out[N,128] = [g_A | Xlast] @ [Wrel ; Wroot] + bias ----------------
#define BM 128
#define BN 128
#define BK 16

__global__ __launch_bounds__(256) void k_gemm(
    const float* __restrict__ Xlast,   // [N,128], source for k in [2048,2176)
    const float* __restrict__ Wrel,    // [2048,128]
    const float* __restrict__ Wroot,   // [128,128]
    const float* __restrict__ bias,    // [128]
    float* __restrict__ out)           // [N,128]
{
    __shared__ float As[BK][BM + 4];
    __shared__ float Bs[BK][BN];

    int tid = threadIdx.x;
    int tx = tid & 15;
    int ty = tid >> 4;
    int m0 = blockIdx.x * BM;

    float acc[8][8];
    #pragma unroll
    for (int i = 0; i < 8; i++)
        #pragma unroll
        for (int j = 0; j < 8; j++) acc[i][j] = 0.f;

    // A-tile load mapping: 512 float4 slots (128 rows x 4 float4/row), 2 per thread
    int arow0 = tid >> 2;          // rows 0..63
    int ac4   = tid & 3;
    int arow1 = arow0 + 64;        // rows 64..127
    // B-tile load mapping: 512 float4 slots (16 rows x 32 float4/row), 2 per thread
    int bk0 = tid >> 5;            // k rows 0..7
    int bc4 = tid & 31;
    int bk1 = bk0 + 8;

    for (int kb = 0; kb < KT; kb += BK) {
        const float* Ap; size_t lda; const float* Bp;
        if (kb < K1) { Ap = g_A + kb;            lda = K1; Bp = Wrel + (size_t)kb * CC; }
        else         { Ap = Xlast + (kb - K1);   lda = CC; Bp = Wroot + (size_t)(kb - K1) * CC; }

        {   // load A tile, transposed to As[k][m]
            int gr = m0 + arow0;
            float4 v = (gr < NN) ? *(const float4*)(Ap + (size_t)gr * lda + ac4 * 4)
                                 : make_float4(0.f, 0.f, 0.f, 0.f);
            As[ac4 * 4 + 0][arow0] = v.x; As[ac4 * 4 + 1][arow0] = v.y;
            As[ac4 * 4 + 2][arow0] = v.z; As[ac4 * 4 + 3][arow0] = v.w;
            gr = m0 + arow1;
            v = (gr < NN) ? *(const float4*)(Ap + (size_t)gr * lda + ac4 * 4)
                          : make_float4(0.f, 0.f, 0.f, 0.f);
            As[ac4 * 4 + 0][arow1] = v.x; As[ac4 * 4 + 1][arow1] = v.y;
            As[ac4 * 4 + 2][arow1] = v.z; As[ac4 * 4 + 3][arow1] = v.w;
        }
        {   // load B tile
            float4 v = *(const float4*)(Bp + (size_t)bk0 * CC + bc4 * 4);
            *(float4*)&Bs[bk0][bc4 * 4] = v;
            v = *(const float4*)(Bp + (size_t)bk1 * CC + bc4 * 4);
            *(float4*)&Bs[bk1][bc4 * 4] = v;
        }
        __syncthreads();

        #pragma unroll
        for (int kk = 0; kk < BK; kk++) {
            float a[8], b[8];
            float4 t;
            t = *(float4*)&As[kk][ty * 8];     a[0] = t.x; a[1] = t.y; a[2] = t.z; a[3] = t.w;
            t = *(float4*)&As[kk][ty * 8 + 4]; a[4] = t.x; a[5] = t.y; a[6] = t.z; a[7] = t.w;
            t = *(float4*)&Bs[kk][tx * 8];     b[0] = t.x; b[1] = t.y; b[2] = t.z; b[3] = t.w;
            t = *(float4*)&Bs[kk][tx * 8 + 4]; b[4] = t.x; b[5] = t.y; b[6] = t.z; b[7] = t.w;
            #pragma unroll
            for (int i = 0; i < 8; i++)
                #pragma unroll
                for (int j = 0; j < 8; j++) acc[i][j] += a[i] * b[j];
        }
        __syncthreads();
    }

    #pragma unroll
    for (int i = 0; i < 8; i++) {
        int gr = m0 + ty * 8 + i;
        if (gr < NN) {
            #pragma unroll
            for (int j = 0; j < 8; j++) {
                int gc = tx * 8 + j;
                out[(size_t)gr * CC + gc] = acc[i][j] + bias[gc];
            }
        }
    }
}

// ---------------- BatchNorm ----------------
__global__ void k_bnstats(const float* __restrict__ h) {
    int tid = threadIdx.x;
    int c = tid & (CC - 1);
    int half = tid >> 7;                 // 0 or 1
    float s = 0.f, q = 0.f;
    for (int row = blockIdx.x * 2 + half; row < NN; row += gridDim.x * 2) {
        float v = h[(size_t)row * CC + c];
        s += v; q += v * v;
    }
    __shared__ float sh[256], shq[256];
    sh[tid] = s; shq[tid] = q;
    __syncthreads();
    if (tid < CC) {
        atomicAdd(&g_bnsum[c], sh[tid] + sh[tid + CC]);
        atomicAdd(&g_bnsq[c],  shq[tid] + shq[tid + CC]);
    }
}

__global__ void k_bnfinal(const float* __restrict__ bnw, const float* __restrict__ bnb) {
    int c = threadIdx.x;
    if (c >= CC) return;
    float mu = g_bnsum[c] / (float)NN;
    float var = g_bnsq[c] / (float)NN - mu * mu;
    float sc = bnw[c] * rsqrtf(var + EPS);
    g_scale[c] = sc;
    g_shift[c] = bnb[c] - mu * sc;
}

__global__ void k_bnapply(float* __restrict__ h) {
    size_t i = (size_t)blockIdx.x * blockDim.x + threadIdx.x;  // float4 index
    size_t tot = (size_t)NN * CC / 4;
    if (i >= tot) return;
    int c4 = (int)(i & 31);     // 32 float4 per row
    float4 v = ((float4*)h)[i];
    float4 sc = ((const float4*)g_scale)[c4];
    float4 sf = ((const float4*)g_shift)[c4];
    v.x = fmaxf(0.f, v.x * sc.x + sf.x);
    v.y = fmaxf(0.f, v.y * sc.y + sf.y);
    v.z = fmaxf(0.f, v.z * sc.z + sf.z);
    v.w = fmaxf(0.f, v.w * sc.w + sf.w);
    ((float4*)h)[i] = v;
}

// ---------------- edge_attr passthrough ----------------
__global__ void k_copyattr(const float* __restrict__ ea, float* __restrict__ out) {
    size_t i = (size_t)blockIdx.x * blockDim.x + threadIdx.x;  // float4 index
    size_t tot = (size_t)EE * 8 / 4;
    if (i < tot) ((float4*)out)[i] = ((const float4*)ea)[i];
}

// ---------------- launch ----------------
extern "C" void kernel_launch(void* const* d_in, const int* in_sizes, int n_in,
                              void* d_out, int out_size) {
    const float* x     = (const float*)d_in[0];
    const int*   ei    = (const int*)d_in[1];   // [2,E]: src row, then dst row
    const float* eattr = (const float*)d_in[2];
    const int*   et    = (const int*)d_in[3];
    const float* W1    = (const float*)d_in[4];
    const float* root1 = (const float*)d_in[5];
    const float* b1    = (const float*)d_in[6];
    const float* bnw   = (const float*)d_in[7];
    const float* bnb   = (const float*)d_in[8];
    const float* W2    = (const float*)d_in[9];
    const float* root2 = (const float*)d_in[10];
    const float* b2    = (const float*)d_in[11];
    float* out = (float*)d_out;

    float* h = nullptr;
    cudaGetSymbolAddress((void**)&h, g_h);

    const int T = 256;
    int blksNR   = (NN * RR + T - 1) / T;
    int blksE    = (EE + T - 1) / T;
    int blksScat = (EE * 32 + T - 1) / T;
    int blksZA   = (int)(((size_t)NN * K1 / 4 + T - 1) / T);
    int blksBNap = (int)(((size_t)NN * CC / 4 + T - 1) / T);
    int blksGemm = (NN + BM - 1) / BM;
    int blksAttr = (int)(((size_t)EE * 8 / 4 + T - 1) / T);

    // structure prep (shared by both layers)
    k_init<<<blksNR, T>>>();
    k_count<<<blksE, T>>>(ei, et);
    k_winv<<<blksNR, T>>>();

    // ----- layer 1 -----
    k_zeroA<<<blksZA, T>>>();
    k_scatter<<<blksScat, T>>>(ei, et, x);
    k_gemm<<<blksGemm, 256>>>(x, W1, root1, b1, h);

    // BN + ReLU
    k_bnstats<<<512, 256>>>(h);
    k_bnfinal<<<1, 128>>>(bnw, bnb);
    k_bnapply<<<blksBNap, T>>>(h);

    // ----- layer 2 -----
    k_zeroA<<<blksZA, T>>>();
    k_scatter<<<blksScat, T>>>(ei, et, h);
    k_gemm<<<blksGemm, 256>>>(h, W2, root2, b2, out);

    // tuple second element
    k_copyattr<<<blksAttr, T>>>(eattr, out + (size_t)NN * CC);
}

// round 2
// speedup vs baseline: 1.4174x; 1.4174x over previous
#include <cuda_runtime.h>
#include <cstdint>

#define NN 50000
#define EE 800000
#define RR 16
#define CC 128
#define K1 2048            // R*C
#define KT 2176            // K1 + C
#define EPS 1e-5f

// ---------------- scratch (module-load allocated, legal) ----------------
__device__ float g_A[(size_t)NN * K1];       // 409.6 MB aggregated features
__device__ float g_h[(size_t)NN * CC];       // hidden activations
__device__ int   g_cnt[NN * RR];
__device__ float g_winv[NN * RR];
__device__ float g_bnsum[CC];
__device__ float g_bnsq[CC];
__device__ float g_scale[CC];
__device__ float g_shift[CC];

// ---------------- init: zero counts + BN accumulators ----------------
__global__ void k_init() {
    int i = blockIdx.x * blockDim.x + threadIdx.x;
    if (i < NN * RR) g_cnt[i] = 0;
    if (i < CC) { g_bnsum[i] = 0.f; g_bnsq[i] = 0.f; }
}

// ---------------- per-(dst,rel) edge counts ----------------
__global__ void k_count(const int* __restrict__ ei, const int* __restrict__ et) {
    int e = blockIdx.x * blockDim.x + threadIdx.x;
    if (e >= EE) return;
    int dst = ei[EE + e];
    int r = et[e]; if (r > RR - 1) r = RR - 1;
    atomicAdd(&g_cnt[dst * RR + r], 1);
}

__global__ void k_winv() {
    int i = blockIdx.x * blockDim.x + threadIdx.x;
    if (i >= NN * RR) return;
    int c = g_cnt[i];
    g_winv[i] = 1.0f / (float)(c > 0 ? c : 1);
}

// ---------------- zero the aggregation buffer ----------------
__global__ void k_zeroA() {
    size_t i = (size_t)blockIdx.x * blockDim.x + threadIdx.x;   // float4 index
    size_t tot = (size_t)NN * K1 / 4;
    if (i < tot) ((float4*)g_A)[i] = make_float4(0.f, 0.f, 0.f, 0.f);
}

// ---------------- scatter: A[dst, rel*128 + c] += w * feat[src, c] ----------------
__global__ void k_scatter(const int* __restrict__ ei, const int* __restrict__ et,
                          const float* __restrict__ feat) {
    int gt = blockIdx.x * blockDim.x + threadIdx.x;
    int e = gt >> 5;
    int lane = gt & 31;
    if (e >= EE) return;
    int src = ei[e];
    int dst = ei[EE + e];
    int r = et[e]; if (r > RR - 1) r = RR - 1;
    float w = g_winv[dst * RR + r];
    const float4* xs = (const float4*)(feat + (size_t)src * CC);
    float* aout = g_A + (size_t)dst * K1 + r * CC;
    float4 v = xs[lane];
    atomicAdd(aout + lane * 4 + 0, w * v.x);
    atomicAdd(aout + lane * 4 + 1, w * v.y);
    atomicAdd(aout + lane * 4 + 2, w * v.z);
    atomicAdd(aout + lane * 4 + 3, w * v.w);
}

// =====================================================================
// Tensor-core GEMM: out[N,128] = [g_A | Xlast] @ [Wrel ; Wroot] + bias
// bf16 3-term split emulation of fp32 (a_hi*b_hi + a_hi*b_lo + a_lo*b_hi)
// =====================================================================
#define BM 128
#define BN 128
#define BK 32
#define BKP 36                        // row pad (floats), 144B = 16B aligned
#define TSTR (128 * BKP)              // floats per stage

__device__ __forceinline__ void cp16(uint32_t dst, const void* src, int bytes) {
    asm volatile("cp.async.cg.shared.global [%0], [%1], 16, %2;"
                 :: "r"(dst), "l"(src), "r"(bytes));
}
__device__ __forceinline__ void cp_commit() { asm volatile("cp.async.commit_group;"); }
__device__ __forceinline__ void cp_wait0()  { asm volatile("cp.async.wait_group 0;"); }

__device__ __forceinline__ uint32_t pack_bf16(float f0, float f1) {
    uint32_t r;
    asm("cvt.rn.bf16x2.f32 %0, %1, %2;" : "=r"(r) : "f"(f1), "f"(f0));
    return r;   // low 16 = f0, high 16 = f1
}
__device__ __forceinline__ void split2(float f0, float f1, uint32_t& hi, uint32_t& lo) {
    hi = pack_bf16(f0, f1);
    float h0 = __uint_as_float(hi << 16);
    float h1 = __uint_as_float(hi & 0xFFFF0000u);
    lo = pack_bf16(f0 - h0, f1 - h1);
}
__device__ __forceinline__ void mma16816(float* c, const uint32_t* a, const uint32_t* b) {
    asm volatile("mma.sync.aligned.m16n8k16.row.col.f32.bf16.bf16.f32 "
        "{%0,%1,%2,%3}, {%4,%5,%6,%7}, {%8,%9}, {%0,%1,%2,%3};"
        : "+f"(c[0]), "+f"(c[1]), "+f"(c[2]), "+f"(c[3])
        : "r"(a[0]), "r"(a[1]), "r"(a[2]), "r"(a[3]), "r"(b[0]), "r"(b[1]));
}

__global__ __launch_bounds__(256, 1) void k_gemm(
    const float* __restrict__ Xlast,   // [N,128], k in [2048,2176)
    const float* __restrict__ Wrel,    // [2048,128]
    const float* __restrict__ Wroot,   // [128,128]
    const float* __restrict__ bias,    // [128]
    float* __restrict__ out)           // [N,128]
{
    extern __shared__ float smem[];
    float* As = smem;                  // 2 stages, [128][BKP]
    float* Bs = smem + 2 * TSTR;       // 2 stages, [128][BKP] (n-major, transposed)

    const int tid  = threadIdx.x;
    const int lane = tid & 31;
    const int wid  = tid >> 5;
    const int g    = lane >> 2;
    const int tg   = lane & 3;
    const int warpRow = (wid & 3) * 32;
    const int warpCol = (wid >> 2) * 64;
    const int m0 = blockIdx.x * BM;

    uint32_t sA_base;
    {
        uint64_t t = __cvta_generic_to_shared(As);
        sA_base = (uint32_t)t;
    }

    float acc[2][8][4];
    #pragma unroll
    for (int mi = 0; mi < 2; mi++)
        #pragma unroll
        for (int ni = 0; ni < 8; ni++)
            #pragma unroll
            for (int q = 0; q < 4; q++) acc[mi][ni][q] = 0.f;

    const int ntiles = KT / BK;   // 68

    // A-tile cp.async mapping: thread -> (row = tid>>3 + 32p, chunk = tid&7)
    const int arow = tid >> 3;
    const int achk = tid & 7;
    // B-tile load mapping: kRow = tid&31, c4 group = tid>>5
    const int kRow = tid & 31;
    const int c4   = tid >> 5;

    float4 breg[4];

    auto issueA = [&](int stage, int kt) {
        int kb = kt * BK;
        const float* base; size_t lda;
        if (kb < K1) { base = g_A + kb;          lda = K1; }
        else         { base = Xlast + (kb - K1); lda = CC; }
        #pragma unroll
        for (int p = 0; p < 4; p++) {
            int row = arow + p * 32;
            int gr = m0 + row;
            bool ok = gr < NN;
            uint32_t dst = sA_base + (uint32_t)((stage * TSTR + row * BKP + achk * 4) * 4);
            const float* src = base + (ok ? ((size_t)gr * lda + achk * 4) : 0);
            cp16(dst, src, ok ? 16 : 0);
        }
    };
    auto ldgB = [&](int kt) {
        int kb = kt * BK;
        const float* Bp = (kb < K1) ? (Wrel + (size_t)kb * CC)
                                    : (Wroot + (size_t)(kb - K1) * CC);
        #pragma unroll
        for (int j = 0; j < 4; j++)
            breg[j] = __ldg((const float4*)(Bp + (size_t)kRow * CC + (c4 + j * 8) * 4));
    };
    auto stsB = [&](int stage) {
        float* B = Bs + stage * TSTR;
        #pragma unroll
        for (int j = 0; j < 4; j++) {
            int n = (c4 + j * 8) * 4;
            B[(n + 0) * BKP + kRow] = breg[j].x;
            B[(n + 1) * BKP + kRow] = breg[j].y;
            B[(n + 2) * BKP + kRow] = breg[j].z;
            B[(n + 3) * BKP + kRow] = breg[j].w;
        }
    };

    // prologue
    issueA(0, 0); cp_commit();
    ldgB(0);
    cp_wait0();
    stsB(0);
    __syncthreads();

    for (int kt = 0; kt < ntiles; kt++) {
        int cur = kt & 1, nxt = cur ^ 1;
        bool more = (kt + 1 < ntiles);
        if (more) { issueA(nxt, kt + 1); cp_commit(); ldgB(kt + 1); }

        const float* A = As + cur * TSTR;
        const float* B = Bs + cur * TSTR;

        #pragma unroll
        for (int ks = 0; ks < 2; ks++) {
            int kk = ks * 16;
            uint32_t ahi[2][4], alo[2][4];
            #pragma unroll
            for (int mi = 0; mi < 2; mi++) {
                int r = warpRow + mi * 16 + g;
                float2 v0 = *(const float2*)&A[(r)     * BKP + kk + 2 * tg];
                float2 v1 = *(const float2*)&A[(r + 8) * BKP + kk + 2 * tg];
                float2 v2 = *(const float2*)&A[(r)     * BKP + kk + 2 * tg + 8];
                float2 v3 = *(const float2*)&A[(r + 8) * BKP + kk + 2 * tg + 8];
                split2(v0.x, v0.y, ahi[mi][0], alo[mi][0]);
                split2(v1.x, v1.y, ahi[mi][1], alo[mi][1]);
                split2(v2.x, v2.y, ahi[mi][2], alo[mi][2]);
                split2(v3.x, v3.y, ahi[mi][3], alo[mi][3]);
            }
            uint32_t bhi[8][2], blo[8][2];
            #pragma unroll
            for (int ni = 0; ni < 8; ni++) {
                int n = warpCol + ni * 8 + g;
                float2 w0 = *(const float2*)&B[n * BKP + kk + 2 * tg];
                float2 w1 = *(const float2*)&B[n * BKP + kk + 2 * tg + 8];
                split2(w0.x, w0.y, bhi[ni][0], blo[ni][0]);
                split2(w1.x, w1.y, bhi[ni][1], blo[ni][1]);
            }
            #pragma unroll
            for (int mi = 0; mi < 2; mi++)
                #pragma unroll
                for (int ni = 0; ni < 8; ni++) {
                    mma16816(acc[mi][ni], ahi[mi], bhi[ni]);
                    mma16816(acc[mi][ni], ahi[mi], blo[ni]);
                    mma16816(acc[mi][ni], alo[mi], bhi[ni]);
                }
        }

        if (more) {
            cp_wait0();
            __syncthreads();
            stsB(nxt);
        }
        __syncthreads();
    }

    // epilogue: bias + store
    #pragma unroll
    for (int ni = 0; ni < 8; ni++) {
        int col = warpCol + ni * 8 + 2 * tg;
        float2 bv = *(const float2*)&bias[col];
        #pragma unroll
        for (int mi = 0; mi < 2; mi++) {
            int r0 = m0 + warpRow + mi * 16 + g;
            int r1 = r0 + 8;
            if (r0 < NN) {
                float2 o = make_float2(acc[mi][ni][0] + bv.x, acc[mi][ni][1] + bv.y);
                *(float2*)&out[(size_t)r0 * CC + col] = o;
            }
            if (r1 < NN) {
                float2 o = make_float2(acc[mi][ni][2] + bv.x, acc[mi][ni][3] + bv.y);
                *(float2*)&out[(size_t)r1 * CC + col] = o;
            }
        }
    }
}

// ---------------- BatchNorm ----------------
__global__ void k_bnstats(const float* __restrict__ h) {
    int tid = threadIdx.x;
    int c = tid & (CC - 1);
    int half = tid >> 7;                 // 0 or 1
    float s = 0.f, q = 0.f;
    for (int row = blockIdx.x * 2 + half; row < NN; row += gridDim.x * 2) {
        float v = h[(size_t)row * CC + c];
        s += v; q += v * v;
    }
    __shared__ float sh[256], shq[256];
    sh[tid] = s; shq[tid] = q;
    __syncthreads();
    if (tid < CC) {
        atomicAdd(&g_bnsum[c], sh[tid] + sh[tid + CC]);
        atomicAdd(&g_bnsq[c],  shq[tid] + shq[tid + CC]);
    }
}

__global__ void k_bnfinal(const float* __restrict__ bnw, const float* __restrict__ bnb) {
    int c = threadIdx.x;
    if (c >= CC) return;
    float mu = g_bnsum[c] / (float)NN;
    float var = g_bnsq[c] / (float)NN - mu * mu;
    float sc = bnw[c] * rsqrtf(var + EPS);
    g_scale[c] = sc;
    g_shift[c] = bnb[c] - mu * sc;
}

__global__ void k_bnapply(float* __restrict__ h) {
    size_t i = (size_t)blockIdx.x * blockDim.x + threadIdx.x;  // float4 index
    size_t tot = (size_t)NN * CC / 4;
    if (i >= tot) return;
    int c4 = (int)(i & 31);     // 32 float4 per row
    float4 v = ((float4*)h)[i];
    float4 sc = ((const float4*)g_scale)[c4];
    float4 sf = ((const float4*)g_shift)[c4];
    v.x = fmaxf(0.f, v.x * sc.x + sf.x);
    v.y = fmaxf(0.f, v.y * sc.y + sf.y);
    v.z = fmaxf(0.f, v.z * sc.z + sf.z);
    v.w = fmaxf(0.f, v.w * sc.w + sf.w);
    ((float4*)h)[i] = v;
}

// ---------------- edge_attr passthrough ----------------
__global__ void k_copyattr(const float* __restrict__ ea, float* __restrict__ out) {
    size_t i = (size_t)blockIdx.x * blockDim.x + threadIdx.x;  // float4 index
    size_t tot = (size_t)EE * 8 / 4;
    if (i < tot) ((float4*)out)[i] = ((const float4*)ea)[i];
}

// ---------------- launch ----------------
extern "C" void kernel_launch(void* const* d_in, const int* in_sizes, int n_in,
                              void* d_out, int out_size) {
    const float* x     = (const float*)d_in[0];
    const int*   ei    = (const int*)d_in[1];   // [2,E]: src row, then dst row
    const float* eattr = (const float*)d_in[2];
    const int*   et    = (const int*)d_in[3];
    const float* W1    = (const float*)d_in[4];
    const float* root1 = (const float*)d_in[5];
    const float* b1    = (const float*)d_in[6];
    const float* bnw   = (const float*)d_in[7];
    const float* bnb   = (const float*)d_in[8];
    const float* W2    = (const float*)d_in[9];
    const float* root2 = (const float*)d_in[10];
    const float* b2    = (const float*)d_in[11];
    float* out = (float*)d_out;

    float* h = nullptr;
    cudaGetSymbolAddress((void**)&h, g_h);

    static bool configured = false;
    if (!configured) {
        cudaFuncSetAttribute(k_gemm, cudaFuncAttributeMaxDynamicSharedMemorySize,
                             4 * TSTR * sizeof(float));
        configured = true;
    }

    const int T = 256;
    int blksNR   = (NN * RR + T - 1) / T;
    int blksE    = (EE + T - 1) / T;
    int blksScat = (EE * 32 + T - 1) / T;
    int blksZA   = (int)(((size_t)NN * K1 / 4 + T - 1) / T);
    int blksBNap = (int)(((size_t)NN * CC / 4 + T - 1) / T);
    int blksGemm = (NN + BM - 1) / BM;
    int blksAttr = (int)(((size_t)EE * 8 / 4 + T - 1) / T);
    size_t gemmSmem = 4 * TSTR * sizeof(float);

    // structure prep (shared by both layers)
    k_init<<<blksNR, T>>>();
    k_count<<<blksE, T>>>(ei, et);
    k_winv<<<blksNR, T>>>();

    // ----- layer 1 -----
    k_zeroA<<<blksZA, T>>>();
    k_scatter<<<blksScat, T>>>(ei, et, x);
    k_gemm<<<blksGemm, 256, gemmSmem>>>(x, W1, root1, b1, h);

    // BN + ReLU
    k_bnstats<<<512, 256>>>(h);
    k_bnfinal<<<1, 128>>>(bnw, bnb);
    k_bnapply<<<blksBNap, T>>>(h);

    // ----- layer 2 -----
    k_zeroA<<<blksZA, T>>>();
    k_scatter<<<blksScat, T>>>(ei, et, h);
    k_gemm<<<blksGemm, 256, gemmSmem>>>(h, W2, root2, b2, out);

    // tuple second element
    k_copyattr<<<blksAttr, T>>>(eattr, out + (size_t)NN * CC);
}

// round 3
// speedup vs baseline: 2.6796x; 1.8905x over previous
#include <cuda_runtime.h>
#include <cuda_bf16.h>
#include <cstdint>

#define NN 50000
#define EE 800000
#define RR 16
#define CC 128
#define K1 2048            // R*C
#define YN 2176            // K1 + C  (Y = X @ [W_all | root])
#define NT 17              // YN / 128 n-tiles
#define EPS 1e-5f

// smem geometry for GEMM tiles: 128 x 136 bf16 (word stride 68 -> conflict-free)
#define SAK 136
#define ABYTES (128 * SAK * 2)     // 34816 bytes per tile array
#define GEMM_SMEM (6 * ABYTES)     // Ahi,Alo + 2 stages x (Bhi,Blo) = 208896

// ---------------- scratch ----------------
__device__ float    g_Y[(size_t)NN * YN];    // 435.2 MB transformed features
__device__ float    g_h[(size_t)NN * CC];    // hidden activations (pre-BN)
__device__ uint32_t g_ahi[NN * 64];          // A operand bf16-hi (pairs)
__device__ uint32_t g_alo[NN * 64];          // A operand bf16-lo
__device__ __nv_bfloat16 g_bh[2 * YN * CC];  // packed B hi (both layers)
__device__ __nv_bfloat16 g_bl[2 * YN * CC];  // packed B lo
__device__ int   g_cnt[NN * RR];
__device__ float g_winv[NN * RR];
__device__ int   g_deg[NN];
__device__ int   g_rowptr[NN];
__device__ int   g_cursor[NN];
__device__ int   g_bsumscan[64];
__device__ int   g_edge[EE];                 // sorted-by-dst: src | (rel<<20)
__device__ float g_bnsum[CC];
__device__ float g_bnsq[CC];
__device__ float g_scale[CC];
__device__ float g_shift[CC];

// ---------------- small helpers ----------------
__device__ __forceinline__ void cp16(uint32_t dst, const void* src, int bytes) {
    asm volatile("cp.async.cg.shared.global [%0], [%1], 16, %2;"
                 :: "r"(dst), "l"(src), "r"(bytes));
}
__device__ __forceinline__ void cp_commit() { asm volatile("cp.async.commit_group;"); }

__device__ __forceinline__ uint32_t pack_bf16(float f0, float f1) {
    uint32_t r;
    asm("cvt.rn.bf16x2.f32 %0, %1, %2;" : "=r"(r) : "f"(f1), "f"(f0));
    return r;   // low 16 = f0, high 16 = f1
}
__device__ __forceinline__ void split2(float f0, float f1, uint32_t& hi, uint32_t& lo) {
    hi = pack_bf16(f0, f1);
    float h0 = __uint_as_float(hi << 16);
    float h1 = __uint_as_float(hi & 0xFFFF0000u);
    lo = pack_bf16(f0 - h0, f1 - h1);
}
__device__ __forceinline__ void mma16816(float* c, const uint32_t* a, const uint32_t* b) {
    asm volatile("mma.sync.aligned.m16n8k16.row.col.f32.bf16.bf16.f32 "
        "{%0,%1,%2,%3}, {%4,%5,%6,%7}, {%8,%9}, {%0,%1,%2,%3};"
        : "+f"(c[0]), "+f"(c[1]), "+f"(c[2]), "+f"(c[3])
        : "r"(a[0]), "r"(a[1]), "r"(a[2]), "r"(a[3]), "r"(b[0]), "r"(b[1]));
}

// ---------------- structure prep ----------------
__global__ void k_init() {
    int i = blockIdx.x * blockDim.x + threadIdx.x;
    if (i < NN * RR) g_cnt[i] = 0;
    if (i < CC) { g_bnsum[i] = 0.f; g_bnsq[i] = 0.f; }
}
__global__ void k_count(const int* __restrict__ ei, const int* __restrict__ et) {
    int e = blockIdx.x * blockDim.x + threadIdx.x;
    if (e >= EE) return;
    int dst = ei[EE + e];
    int r = et[e]; if (r > RR - 1) r = RR - 1;
    atomicAdd(&g_cnt[dst * RR + r], 1);
}
__global__ void k_winv_deg() {
    int n = blockIdx.x * blockDim.x + threadIdx.x;
    if (n >= NN) return;
    int d = 0;
    #pragma unroll
    for (int r = 0; r < RR; r++) {
        int c = g_cnt[n * RR + r];
        d += c;
        g_winv[n * RR + r] = 1.0f / (float)(c > 0 ? c : 1);
    }
    g_deg[n] = d;
}
__global__ void k_scan1() {   // 49 blocks x 1024
    __shared__ int sh[1024];
    int t = threadIdx.x;
    int idx = blockIdx.x * 1024 + t;
    int v = (idx < NN) ? g_deg[idx] : 0;
    sh[t] = v;
    __syncthreads();
    for (int o = 1; o < 1024; o <<= 1) {
        int add = (t >= o) ? sh[t - o] : 0;
        __syncthreads();
        sh[t] += add;
        __syncthreads();
    }
    if (idx < NN) g_rowptr[idx] = sh[t] - v;       // exclusive, pre-offset
    if (t == 1023) g_bsumscan[blockIdx.x] = sh[t];
}
__global__ void k_scan2() {   // 1 thread scans 49 block sums
    if (threadIdx.x == 0) {
        int acc = 0;
        for (int b = 0; b < 49; b++) {
            int v = g_bsumscan[b];
            g_bsumscan[b] = acc;
            acc += v;
        }
    }
}
__global__ void k_scan3() {
    int idx = blockIdx.x * blockDim.x + threadIdx.x;
    if (idx >= NN) return;
    int p = g_rowptr[idx] + g_bsumscan[idx >> 10];
    g_rowptr[idx] = p;
    g_cursor[idx] = p;
}
__global__ void k_place(const int* __restrict__ ei, const int* __restrict__ et) {
    int e = blockIdx.x * blockDim.x + threadIdx.x;
    if (e >= EE) return;
    int src = ei[e];
    int dst = ei[EE + e];
    int r = et[e]; if (r > RR - 1) r = RR - 1;
    int pos = atomicAdd(&g_cursor[dst], 1);
    g_edge[pos] = src | (r << 20);
}

// ---------------- operand prep ----------------
__global__ void k_packB(const float* __restrict__ W, const float* __restrict__ root,
                        __nv_bfloat16* __restrict__ bh, __nv_bfloat16* __restrict__ bl) {
    int idx = blockIdx.x * blockDim.x + threadIdx.x;   // n*128 + k
    if (idx >= YN * CC) return;
    int n = idx >> 7, k = idx & 127;
    float v = (n < K1) ? W[((size_t)(n >> 7) << 14) + (k << 7) + (n & 127)]
                       : root[(k << 7) + (n - K1)];
    __nv_bfloat16 h = __float2bfloat16(v);
    float hf = __bfloat162float(h);
    bh[idx] = h;
    bl[idx] = __float2bfloat16(v - hf);
}
__global__ void k_splitX(const float* __restrict__ x) {
    int i = blockIdx.x * blockDim.x + threadIdx.x;     // float2 units
    if (i >= NN * 64) return;
    float2 v = ((const float2*)x)[i];
    uint32_t hi, lo;
    split2(v.x, v.y, hi, lo);
    g_ahi[i] = hi; g_alo[i] = lo;
}

// =====================================================================
// GEMM: Y[N, 2176] = A[N,128] @ B[128, 2176]   (3-term bf16 split, pre-split)
// Block: 128 rows of A resident in smem; loops all 17 n-tiles.
// =====================================================================
__global__ __launch_bounds__(256, 1) void k_gemm(
    const __nv_bfloat16* __restrict__ Ahg,
    const __nv_bfloat16* __restrict__ Alg,
    const __nv_bfloat16* __restrict__ Bhg,   // [2176][128] n-major
    const __nv_bfloat16* __restrict__ Blg,
    float* __restrict__ Y)
{
    extern __shared__ char smem[];
    const int tid = threadIdx.x, lane = tid & 31, wid = tid >> 5;
    const int g = lane >> 2, tg = lane & 3;
    const int warpRow = (wid & 3) * 32, warpCol = (wid >> 2) * 64;
    const int m0 = blockIdx.x * 128;
    uint32_t sb = (uint32_t)__cvta_generic_to_shared(smem);

    // A prologue (hi + lo)
    #pragma unroll
    for (int it = 0; it < 8; it++) {
        int c = tid + it * 256;
        int row = c >> 4, chk = c & 15;
        int gr = m0 + row;
        bool ok = gr < NN;
        size_t off = ok ? ((size_t)gr * CC + chk * 8) : 0;
        cp16(sb + row * 272 + chk * 16, Ahg + off, ok ? 16 : 0);
        cp16(sb + ABYTES + row * 272 + chk * 16, Alg + off, ok ? 16 : 0);
    }
    auto loadB = [&](int stage, int nt) {
        uint32_t bb = sb + 2 * ABYTES + stage * (2 * ABYTES);
        #pragma unroll
        for (int it = 0; it < 8; it++) {
            int c = tid + it * 256;
            int row = c >> 4, chk = c & 15;
            size_t goff = (size_t)(nt * CC + row) * CC + chk * 8;
            cp16(bb + row * 272 + chk * 16, Bhg + goff, 16);
            cp16(bb + ABYTES + row * 272 + chk * 16, Blg + goff, 16);
        }
    };
    loadB(0, 0);
    cp_commit();

    const uint32_t* Ah32 = (const uint32_t*)smem;
    const uint32_t* Al32 = Ah32 + ABYTES / 4;

    for (int nt = 0; nt < NT; nt++) {
        int cur = nt & 1;
        if (nt + 1 < NT) {
            loadB(cur ^ 1, nt + 1);
            cp_commit();
            asm volatile("cp.async.wait_group 1;");
        } else {
            asm volatile("cp.async.wait_group 0;");
        }
        __syncthreads();

        const uint32_t* Bh32 = (const uint32_t*)(smem + 2 * ABYTES + cur * 2 * ABYTES);
        const uint32_t* Bl32 = Bh32 + ABYTES / 4;

        float acc[2][8][4];
        #pragma unroll
        for (int mi = 0; mi < 2; mi++)
            #pragma unroll
            for (int ni = 0; ni < 8; ni++)
                #pragma unroll
                for (int q = 0; q < 4; q++) acc[mi][ni][q] = 0.f;

        #pragma unroll
        for (int ks = 0; ks < 8; ks++) {
            int kp = ks * 8;
            uint32_t ah[2][4], al[2][4];
            #pragma unroll
            for (int mi = 0; mi < 2; mi++) {
                int r = warpRow + mi * 16 + g;
                ah[mi][0] = Ah32[r * 68 + kp + tg];
                ah[mi][1] = Ah32[(r + 8) * 68 + kp + tg];
                ah[mi][2] = Ah32[r * 68 + kp + tg + 4];
                ah[mi][3] = Ah32[(r + 8) * 68 + kp + tg + 4];
                al[mi][0] = Al32[r * 68 + kp + tg];
                al[mi][1] = Al32[(r + 8) * 68 + kp + tg];
                al[mi][2] = Al32[r * 68 + kp + tg + 4];
                al[mi][3] = Al32[(r + 8) * 68 + kp + tg + 4];
            }
            #pragma unroll
            for (int ni = 0; ni < 8; ni++) {
                int n = warpCol + ni * 8 + g;
                uint32_t bh[2] = { Bh32[n * 68 + kp + tg], Bh32[n * 68 + kp + tg + 4] };
                uint32_t bl[2] = { Bl32[n * 68 + kp + tg], Bl32[n * 68 + kp + tg + 4] };
                mma16816(acc[0][ni], ah[0], bh);
                mma16816(acc[1][ni], ah[1], bh);
                mma16816(acc[0][ni], ah[0], bl);
                mma16816(acc[1][ni], ah[1], bl);
                mma16816(acc[0][ni], al[0], bh);
                mma16816(acc[1][ni], al[1], bh);
            }
        }

        #pragma unroll
        for (int ni = 0; ni < 8; ni++) {
            int col = nt * 128 + warpCol + ni * 8 + 2 * tg;
            #pragma unroll
            for (int mi = 0; mi < 2; mi++) {
                int r0 = m0 + warpRow + mi * 16 + g;
                int r1 = r0 + 8;
                if (r0 < NN)
                    *(float2*)&Y[(size_t)r0 * YN + col] = make_float2(acc[mi][ni][0], acc[mi][ni][1]);
                if (r1 < NN)
                    *(float2*)&Y[(size_t)r1 * YN + col] = make_float2(acc[mi][ni][2], acc[mi][ni][3]);
            }
        }
        __syncthreads();
    }
}

// ---------------- aggregation: warp per dst node, CSR gather ----------------
__global__ __launch_bounds__(256) void k_agg(const float* __restrict__ bias,
                                             float* __restrict__ out) {
    int w = (blockIdx.x * blockDim.x + threadIdx.x) >> 5;
    int lane = threadIdx.x & 31;
    if (w >= NN) return;
    // init: root-transform columns + bias
    float4 acc = *(const float4*)(g_Y + (size_t)w * YN + K1 + lane * 4);
    float4 bv = *(const float4*)(bias + lane * 4);
    acc.x += bv.x; acc.y += bv.y; acc.z += bv.z; acc.w += bv.w;
    int s = g_rowptr[w];
    int d = g_deg[w];
    for (int i = 0; i < d; i++) {
        int rec = g_edge[s + i];
        int src = rec & 0xFFFFF;
        int r = rec >> 20;
        float wgt = g_winv[w * RR + r];
        float4 v = *(const float4*)(g_Y + (size_t)src * YN + r * CC + lane * 4);
        acc.x += wgt * v.x; acc.y += wgt * v.y;
        acc.z += wgt * v.z; acc.w += wgt * v.w;
    }
    *(float4*)(out + (size_t)w * CC + lane * 4) = acc;
}

// ---------------- BatchNorm ----------------
__global__ void k_bnstats(const float* __restrict__ h) {
    int tid = threadIdx.x;
    int c = tid & (CC - 1);
    int half = tid >> 7;
    float s = 0.f, q = 0.f;
    for (int row = blockIdx.x * 2 + half; row < NN; row += gridDim.x * 2) {
        float v = h[(size_t)row * CC + c];
        s += v; q += v * v;
    }
    __shared__ float sh[256], shq[256];
    sh[tid] = s; shq[tid] = q;
    __syncthreads();
    if (tid < CC) {
        atomicAdd(&g_bnsum[c], sh[tid] + sh[tid + CC]);
        atomicAdd(&g_bnsq[c],  shq[tid] + shq[tid + CC]);
    }
}
__global__ void k_bnfinal(const float* __restrict__ bnw, const float* __restrict__ bnb) {
    int c = threadIdx.x;
    if (c >= CC) return;
    float mu = g_bnsum[c] / (float)NN;
    float var = g_bnsq[c] / (float)NN - mu * mu;
    float sc = bnw[c] * rsqrtf(var + EPS);
    g_scale[c] = sc;
    g_shift[c] = bnb[c] - mu * sc;
}
// BN apply + ReLU fused with bf16 hi/lo presplit for layer-2 GEMM
__global__ void k_bnapply_split(const float* __restrict__ h) {
    int i = blockIdx.x * blockDim.x + threadIdx.x;   // float2 units
    if (i >= NN * 64) return;
    int c2 = i & 63;
    float2 v = ((const float2*)h)[i];
    float2 sc = ((const float2*)g_scale)[c2];
    float2 sf = ((const float2*)g_shift)[c2];
    float a0 = fmaxf(0.f, v.x * sc.x + sf.x);
    float a1 = fmaxf(0.f, v.y * sc.y + sf.y);
    uint32_t hi, lo;
    split2(a0, a1, hi, lo);
    g_ahi[i] = hi; g_alo[i] = lo;
}

// ---------------- edge_attr passthrough ----------------
__global__ void k_copyattr(const float* __restrict__ ea, float* __restrict__ out) {
    size_t i = (size_t)blockIdx.x * blockDim.x + threadIdx.x;
    size_t tot = (size_t)EE * 8 / 4;
    if (i < tot) ((float4*)out)[i] = ((const float4*)ea)[i];
}

// ---------------- launch ----------------
extern "C" void kernel_launch(void* const* d_in, const int* in_sizes, int n_in,
                              void* d_out, int out_size) {
    const float* x     = (const float*)d_in[0];
    const int*   ei    = (const int*)d_in[1];
    const float* eattr = (const float*)d_in[2];
    const int*   et    = (const int*)d_in[3];
    const float* W1    = (const float*)d_in[4];
    const float* root1 = (const float*)d_in[5];
    const float* b1    = (const float*)d_in[6];
    const float* bnw   = (const float*)d_in[7];
    const float* bnb   = (const float*)d_in[8];
    const float* W2    = (const float*)d_in[9];
    const float* root2 = (const float*)d_in[10];
    const float* b2    = (const float*)d_in[11];
    float* out = (float*)d_out;

    float* h;  cudaGetSymbolAddress((void**)&h, g_h);
    float* Y;  cudaGetSymbolAddress((void**)&Y, g_Y);
    uint32_t* ahi; cudaGetSymbolAddress((void**)&ahi, g_ahi);
    uint32_t* alo; cudaGetSymbolAddress((void**)&alo, g_alo);
    __nv_bfloat16* bh; cudaGetSymbolAddress((void**)&bh, g_bh);
    __nv_bfloat16* bl; cudaGetSymbolAddress((void**)&bl, g_bl);

    static bool configured = false;
    if (!configured) {
        cudaFuncSetAttribute(k_gemm, cudaFuncAttributeMaxDynamicSharedMemorySize, GEMM_SMEM);
        configured = true;
    }

    const int T = 256;
    int blksNR   = (NN * RR + T - 1) / T;
    int blksE    = (EE + T - 1) / T;
    int blksN    = (NN + T - 1) / T;
    int blksPack = (YN * CC + T - 1) / T;
    int blksSpl  = (NN * 64 + T - 1) / T;
    int blksGemm = (NN + 127) / 128;
    int blksAgg  = (NN * 32 + T - 1) / T;
    int blksAttr = (int)(((size_t)EE * 8 / 4 + T - 1) / T);

    // structure prep (shared by both layers)
    k_init<<<blksNR, T>>>();
    k_count<<<blksE, T>>>(ei, et);
    k_winv_deg<<<blksN, T>>>();
    k_scan1<<<49, 1024>>>();
    k_scan2<<<1, 32>>>();
    k_scan3<<<blksN, T>>>();
    k_place<<<blksE, T>>>(ei, et);

    // operand prep
    k_packB<<<blksPack, T>>>(W1, root1, bh, bl);
    k_packB<<<blksPack, T>>>(W2, root2, bh + (size_t)YN * CC, bl + (size_t)YN * CC);
    k_splitX<<<blksSpl, T>>>(x);

    // ----- layer 1 -----
    k_gemm<<<blksGemm, 256, GEMM_SMEM>>>((__nv_bfloat16*)ahi, (__nv_bfloat16*)alo,
                                         bh, bl, Y);
    k_agg<<<blksAgg, T>>>(b1, h);
    k_bnstats<<<512, 256>>>(h);
    k_bnfinal<<<1, 128>>>(bnw, bnb);
    k_bnapply_split<<<blksSpl, T>>>(h);

    // ----- layer 2 -----
    k_gemm<<<blksGemm, 256, GEMM_SMEM>>>((__nv_bfloat16*)ahi, (__nv_bfloat16*)alo,
                                         bh + (size_t)YN * CC, bl + (size_t)YN * CC, Y);
    k_agg<<<blksAgg, T>>>(b2, out);

    // tuple second element
    k_copyattr<<<blksAttr, T>>>(eattr, out + (size_t)NN * CC);
}